// round 1
// baseline (speedup 1.0000x reference)
#include <cuda_runtime.h>
#include <math.h>

#define L 256
#define CH 32
#define DEPTH 4
#define PLANE (L*L)                 // 65536
#define BUF_ELEMS (32u*CH*PLANE)    // 32 batches * 32 ch * 256 * 256

// Scratch ping-pong buffers (device globals: allocation-free).
__device__ float g_bufA[BUF_ELEMS];
__device__ float g_bufB[BUF_ELEMS];

// ---------------- helpers ----------------

__device__ __forceinline__ float gelu_f(float v) {
    return 0.5f * v * (1.0f + erff(v * 0.7071067811865476f));
}

__device__ __forceinline__ unsigned long long splat2(float w) {
    unsigned long long r;
    asm("mov.b64 %0, {%1, %1};" : "=l"(r) : "f"(w));
    return r;
}

__device__ __forceinline__ void fma2(unsigned long long& d, unsigned long long a, unsigned long long b) {
    asm("fma.rn.f32x2 %0, %1, %2, %0;" : "+l"(d) : "l"(a), "l"(b));
}

__device__ __forceinline__ void unpack2(unsigned long long v, float& lo, float& hi) {
    asm("mov.b64 {%0, %1}, %2;" : "=f"(lo), "=f"(hi) : "l"(v));
}

// ---------------- kernel 1: first layer (1 -> 32 ch) + gelu ----------------
// grid (8, 32, 32), block (32, 8). Writes g_bufA.
__global__ void k_first(const float* __restrict__ x,
                        const float* __restrict__ ci, const float* __restrict__ bi,
                        const float* __restrict__ ai, const float* __restrict__ bias_i,
                        float sign)
{
    __shared__ float w[128];
    int tid = threadIdx.y * 32 + threadIdx.x;
    if (tid < 128) {
        w[tid] = (tid < 32) ? ci[tid]
               : (tid < 64) ? bi[tid - 32]
               : (tid < 96) ? ai[tid - 64]
                            : bias_i[tid - 96];
    }
    __syncthreads();

    int gx = blockIdx.x * 32 + threadIdx.x;
    int gy = blockIdx.y * 8  + threadIdx.y;
    int b  = blockIdx.z;

    const float* xb = x + (b << 16);
    int xm = (gx + 255) & 255, xq = (gx + 1) & 255;
    int ym = (gy + 255) & 255, yq = (gy + 1) & 255;

    float ctr = xb[(gy << 8) + gx];
    float nb  = xb[(ym << 8) + gx] + xb[(yq << 8) + gx]
              + xb[(gy << 8) + xm] + xb[(gy << 8) + xq];
    float dg  = xb[(ym << 8) + xm] + xb[(ym << 8) + xq]
              + xb[(yq << 8) + xm] + xb[(yq << 8) + xq];
    ctr *= sign; nb *= sign; dg *= sign;

    float* outp = g_bufA + ((b * CH) << 16) + (gy << 8) + gx;
    #pragma unroll
    for (int o = 0; o < 32; o++) {
        float v = w[o] * ctr + w[32 + o] * nb + w[64 + o] * dg + w[96 + o];
        outp[o << 16] = gelu_f(v);
    }
}

// ---------------- kernel 2: middle layer (32 -> 32 ch) + gelu ----------------

#define HS_SZ (32*10*34)            // 10880 floats  (halo tile, ch-major)
#define F_SZ  (96*256)              // 24576 floats  (feature matrix [k][p])
#define W_OFF (HS_SZ + F_SZ)        // 35456
#define B_OFF (W_OFF + 96*32)       // 38528
#define SMEM_FLOATS (B_OFF + 32)    // 38560
#define SMEM_BYTES (SMEM_FLOATS * 4) // 154240

// grid (8, 32, 32), block 256 threads.
__global__ void k_mid(const float* __restrict__ wa_g, const float* __restrict__ wb_g,
                      const float* __restrict__ wc_g, const float* __restrict__ bias_g,
                      int layer, int dir)
{
    extern __shared__ float sm[];
    float* Hs = sm;                 // [32][10][34]
    float* F  = sm + HS_SZ;         // [96][256]
    float* Ws = sm + W_OFF;         // [96][32]  (k-major, o contiguous)
    float* bs = sm + B_OFF;         // [32]

    const float* src = dir ? g_bufB : g_bufA;
    float*       dst = dir ? g_bufA : g_bufB;

    int tid = threadIdx.x;
    int tx0 = blockIdx.x * 32, ty0 = blockIdx.y * 8, bb = blockIdx.z;
    const float* inb = src + ((bb * CH) << 16);

    // Phase 1a: halo tile load (periodic wrap)
    for (int t = tid; t < HS_SZ; t += 256) {
        int i   = t / 340;
        int rem = t - i * 340;
        int r   = rem / 34;
        int cc  = rem - r * 34;
        int gy  = (ty0 + r + 255) & 255;
        int gx  = (tx0 + cc + 255) & 255;
        Hs[t] = inb[(i << 16) + (gy << 8) + gx];
    }
    // Phase 1b: weights -> smem, transposed to [k][o]
    {
        const float* wc = wc_g + layer * 1024;
        const float* wb = wb_g + layer * 1024;
        const float* wa = wa_g + layer * 1024;
        for (int t = tid; t < 96 * 32; t += 256) {
            int k = t >> 5, o = t & 31;
            const float* wsrc = (k < 32) ? wc : (k < 64) ? wb : wa;
            Ws[t] = wsrc[(o << 5) + (k & 31)];
        }
        if (tid < 32) bs[tid] = bias_g[layer * 32 + tid];
    }
    __syncthreads();

    // Phase 2: build F = [center; orth-sum; diag-sum], each thread owns pixel p=tid
    {
        int p  = tid;
        int py = p >> 5, px = p & 31;
        int base = (py + 1) * 34 + px + 1;
        #pragma unroll 4
        for (int i = 0; i < 32; i++) {
            const float* h = Hs + i * 340;
            float ctr = h[base];
            float nb  = h[base - 34] + h[base + 34] + h[base - 1]  + h[base + 1];
            float dg  = h[base - 35] + h[base + 35] + h[base - 33] + h[base + 33];
            F[(i << 8)        + p] = ctr;
            F[((i + 32) << 8) + p] = nb;
            F[((i + 64) << 8) + p] = dg;
        }
    }
    __syncthreads();

    // Phase 3: out[o][p] = sum_k Ws[k][o] * F[k][p]; thread tile 4(o) x 8(p), f32x2 packed
    int og = (tid & 7) << 2;        // 4 output channels
    int pg = (tid >> 3) << 3;       // 8 pixels
    unsigned long long acc[4][4] = {};  // 0ull == packed (0.f, 0.f)

    #pragma unroll 4
    for (int k = 0; k < 96; k++) {
        float4 wv = *reinterpret_cast<const float4*>(Ws + (k << 5) + og);
        ulonglong2 fa = *reinterpret_cast<const ulonglong2*>(F + (k << 8) + pg);
        ulonglong2 fb = *reinterpret_cast<const ulonglong2*>(F + (k << 8) + pg + 4);
        unsigned long long w;
        w = splat2(wv.x);
        fma2(acc[0][0], w, fa.x); fma2(acc[0][1], w, fa.y);
        fma2(acc[0][2], w, fb.x); fma2(acc[0][3], w, fb.y);
        w = splat2(wv.y);
        fma2(acc[1][0], w, fa.x); fma2(acc[1][1], w, fa.y);
        fma2(acc[1][2], w, fb.x); fma2(acc[1][3], w, fb.y);
        w = splat2(wv.z);
        fma2(acc[2][0], w, fa.x); fma2(acc[2][1], w, fa.y);
        fma2(acc[2][2], w, fb.x); fma2(acc[2][3], w, fb.y);
        w = splat2(wv.w);
        fma2(acc[3][0], w, fa.x); fma2(acc[3][1], w, fa.y);
        fma2(acc[3][2], w, fb.x); fma2(acc[3][3], w, fb.y);
    }

    // Epilogue: bias + gelu, vectorized float2 store
    int py  = pg >> 5, px0 = pg & 31;
    int gy  = ty0 + py;
    #pragma unroll
    for (int oo = 0; oo < 4; oo++) {
        int o = og + oo;
        float bv = bs[o];
        float* op = dst + ((bb * CH + o) << 16) + (gy << 8) + tx0 + px0;
        #pragma unroll
        for (int j = 0; j < 4; j++) {
            float v0, v1;
            unpack2(acc[oo][j], v0, v1);
            float2 r2 = make_float2(gelu_f(v0 + bv), gelu_f(v1 + bv));
            *reinterpret_cast<float2*>(op + (j << 1)) = r2;
        }
    }
}

// ---------------- kernel 3: last layer (32 -> 1 ch), antisym combine ----------------
// grid (8, 32, 32), block (32, 8). Reads g_bufA. mode 0: out = 0.5*y; mode 1: out -= 0.5*y
__global__ void k_last(const float* __restrict__ co, const float* __restrict__ bo,
                       const float* __restrict__ ao, float* __restrict__ out, int mode)
{
    __shared__ float Hs[HS_SZ];
    __shared__ float ws[96];
    int tx = threadIdx.x, ty = threadIdx.y;
    int tid = ty * 32 + tx;
    int tx0 = blockIdx.x * 32, ty0 = blockIdx.y * 8, b = blockIdx.z;
    const float* inb = g_bufA + ((b * CH) << 16);

    for (int t = tid; t < HS_SZ; t += 256) {
        int i   = t / 340;
        int rem = t - i * 340;
        int r   = rem / 34;
        int cc  = rem - r * 34;
        int gy  = (ty0 + r + 255) & 255;
        int gx  = (tx0 + cc + 255) & 255;
        Hs[t] = inb[(i << 16) + (gy << 8) + gx];
    }
    if (tid < 96) {
        ws[tid] = (tid < 32) ? co[tid] : (tid < 64) ? bo[tid - 32] : ao[tid - 64];
    }
    __syncthreads();

    int base = (ty + 1) * 34 + tx + 1;
    float acc = 0.f;
    #pragma unroll 4
    for (int i = 0; i < 32; i++) {
        const float* h = Hs + i * 340;
        float ctr = h[base];
        float nb  = h[base - 34] + h[base + 34] + h[base - 1]  + h[base + 1];
        float dg  = h[base - 35] + h[base + 35] + h[base - 33] + h[base + 33];
        acc += ws[i] * ctr + ws[32 + i] * nb + ws[64 + i] * dg;
    }

    int gy = ty0 + ty, gx = tx0 + tx;
    int oidx = (b << 16) + (gy << 8) + gx;
    if (mode == 0) out[oidx] = 0.5f * acc;
    else           out[oidx] -= 0.5f * acc;
}

// ---------------- launcher ----------------

extern "C" void kernel_launch(void* const* d_in, const int* in_sizes, int n_in,
                              void* d_out, int out_size)
{
    const float* x      = (const float*)d_in[0];
    const float* ai     = (const float*)d_in[1];
    const float* ao     = (const float*)d_in[2];
    const float* a      = (const float*)d_in[3];
    const float* bi     = (const float*)d_in[4];
    const float* bo     = (const float*)d_in[5];
    const float* b      = (const float*)d_in[6];
    const float* ci     = (const float*)d_in[7];
    const float* co     = (const float*)d_in[8];
    const float* c      = (const float*)d_in[9];
    const float* bias_i = (const float*)d_in[10];
    const float* bias   = (const float*)d_in[11];
    float* out = (float*)d_out;

    cudaFuncSetAttribute(k_mid, cudaFuncAttributeMaxDynamicSharedMemorySize, SMEM_BYTES);

    dim3 grid(8, 32, 32);
    dim3 blk(32, 8);

    for (int s = 0; s < 2; s++) {
        float sign = s ? -1.f : 1.f;
        k_first<<<grid, blk>>>(x, ci, bi, ai, bias_i, sign);
        int dir = 0;
        for (int k = 0; k < DEPTH; k++) {
            k_mid<<<grid, 256, SMEM_BYTES>>>(a, b, c, bias, k, dir);
            dir ^= 1;
        }
        k_last<<<grid, blk>>>(co, bo, ao, out, s);
    }
}

// round 3
// speedup vs baseline: 1.1717x; 1.1717x over previous
#include <cuda_runtime.h>
#include <math.h>

#define L 256
#define CH 32
#define DEPTH 4
#define PLANE (L*L)                 // 65536
#define BUF_ELEMS (32u*CH*PLANE)

// Scratch ping-pong buffers (device globals: allocation-free).
__device__ float g_bufA[BUF_ELEMS];
__device__ float g_bufB[BUF_ELEMS];

// ---------------- helpers ----------------

__device__ __forceinline__ float gelu_f(float v) {
    return 0.5f * v * (1.0f + erff(v * 0.7071067811865476f));
}

__device__ __forceinline__ unsigned long long dup2(float w) {
    unsigned long long r;
    asm("mov.b64 %0, {%1, %1};" : "=l"(r) : "f"(w));
    return r;
}

__device__ __forceinline__ void fma2(unsigned long long& d, unsigned long long a, unsigned long long b) {
    asm("fma.rn.f32x2 %0, %1, %2, %0;" : "+l"(d) : "l"(a), "l"(b));
}

__device__ __forceinline__ void unpack2(unsigned long long v, float& lo, float& hi) {
    asm("mov.b64 {%0, %1}, %2;" : "=f"(lo), "=f"(hi) : "l"(v));
}

// ---------------- k_mid tiling ----------------
// Tile: 16 rows x 32 cols = 512 px, halo 18 x 34. Block = 512 threads.
#define TY 16
#define TX 32
#define PX 512
#define HR 18
#define HCOL 34
#define HCH (HR*HCOL)               // 612 floats per channel
#define HS2 (32*HCH)                // 19584 floats
#define FG_OFF HS2                  // F group: 32*512 = 16384 floats
#define FG_SZ (32*PX)
#define WS_OFFF (FG_OFF + FG_SZ)    // 35968 floats; weights as ulonglong pairs
#define WS_ULL (96*32)              // 3072 ulonglong = 6144 float slots
#define BIAS_OFF (WS_OFFF + 2*WS_ULL) // 42112
#define SMEM_FLOATS (BIAS_OFF + 32)
#define SMEM_BYTES (SMEM_FLOATS*4)    // ~168.6 KB

// grid (8, 16, 32), block 512.
__global__ void __launch_bounds__(512, 1)
k_mid(const float* __restrict__ wa_g, const float* __restrict__ wb_g,
      const float* __restrict__ wc_g, const float* __restrict__ bias_g,
      int layer, int dir)
{
    extern __shared__ float sm[];
    float* Hs = sm;                                       // [32][18][34]
    float* F  = sm + FG_OFF;                              // [32][512]
    unsigned long long* Ws = (unsigned long long*)(sm + WS_OFFF); // [96][32] (w,w) pairs
    float* bs = sm + BIAS_OFF;

    const float* src = dir ? g_bufB : g_bufA;
    float*       dst = dir ? g_bufA : g_bufB;

    int tid = threadIdx.x;
    int tx0 = blockIdx.x * TX, ty0 = blockIdx.y * TY, bb = blockIdx.z;
    const float* inb = src + ((bb * CH) << 16);

    // -------- Phase 1a: halo tile load (periodic wrap) --------
    for (int t = tid; t < HS2; t += 512) {
        int i   = t / HCH;
        int rem = t - i * HCH;
        int r   = rem / HCOL;
        int cc  = rem - r * HCOL;
        int gy  = (ty0 + r + 255) & 255;
        int gx  = (tx0 + cc + 255) & 255;
        Hs[t] = inb[(i << 16) + (gy << 8) + gx];
    }
    // -------- Phase 1b: weights -> smem, transposed [g*32+k][o], duplicated pairs --------
    {
        const float* wc = wc_g + layer * 1024;
        const float* wb = wb_g + layer * 1024;
        const float* wa = wa_g + layer * 1024;
        for (int t = tid; t < WS_ULL; t += 512) {
            int kk = t >> 5, o = t & 31;               // kk = g*32+k
            const float* wsrc = (kk < 32) ? wc : (kk < 64) ? wb : wa;
            Ws[t] = dup2(wsrc[(o << 5) + (kk & 31)]);
        }
        if (tid < 32) bs[tid] = bias_g[layer * 32 + tid];
    }

    // thread tile: 4 outputs x 8 pixels
    int og = (tid & 7) << 2;
    int pg = (tid >> 3) << 3;
    unsigned long long acc[4][4] = {};   // 0ull == (0.f,0.f)

    // pixel owned in phase-2 build
    int p  = tid;
    int py = p >> 5, pxx = p & 31;
    int base = (py + 1) * HCOL + pxx + 1;

    // -------- 3 groups: build F_g then accumulate 32 k-steps --------
    #pragma unroll 1
    for (int g = 0; g < 3; g++) {
        __syncthreads();    // F free for rewrite / (first iter: Hs+Ws ready)
        // build F group: center / orth-sum / diag-sum
        if (g == 0) {
            #pragma unroll 4
            for (int i = 0; i < 32; i++)
                F[(i << 9) + p] = Hs[i * HCH + base];
        } else if (g == 1) {
            #pragma unroll 4
            for (int i = 0; i < 32; i++) {
                const float* h = Hs + i * HCH;
                F[(i << 9) + p] = h[base - HCOL] + h[base + HCOL] + h[base - 1] + h[base + 1];
            }
        } else {
            #pragma unroll 4
            for (int i = 0; i < 32; i++) {
                const float* h = Hs + i * HCH;
                F[(i << 9) + p] = h[base - HCOL - 1] + h[base + HCOL + 1]
                                + h[base - HCOL + 1] + h[base + HCOL - 1];
            }
        }
        __syncthreads();

        const unsigned long long* wp = Ws + (g << 5) * 32;
        #pragma unroll 4
        for (int k = 0; k < 32; k++) {
            ulonglong2 w01 = *reinterpret_cast<const ulonglong2*>(wp + (k << 5) + og);
            ulonglong2 w23 = *reinterpret_cast<const ulonglong2*>(wp + (k << 5) + og + 2);
            ulonglong2 fa  = *reinterpret_cast<const ulonglong2*>(F + (k << 9) + pg);
            ulonglong2 fb  = *reinterpret_cast<const ulonglong2*>(F + (k << 9) + pg + 4);
            fma2(acc[0][0], w01.x, fa.x); fma2(acc[0][1], w01.x, fa.y);
            fma2(acc[0][2], w01.x, fb.x); fma2(acc[0][3], w01.x, fb.y);
            fma2(acc[1][0], w01.y, fa.x); fma2(acc[1][1], w01.y, fa.y);
            fma2(acc[1][2], w01.y, fb.x); fma2(acc[1][3], w01.y, fb.y);
            fma2(acc[2][0], w23.x, fa.x); fma2(acc[2][1], w23.x, fa.y);
            fma2(acc[2][2], w23.x, fb.x); fma2(acc[2][3], w23.x, fb.y);
            fma2(acc[3][0], w23.y, fa.x); fma2(acc[3][1], w23.y, fa.y);
            fma2(acc[3][2], w23.y, fb.x); fma2(acc[3][3], w23.y, fb.y);
        }
    }

    // -------- Epilogue: bias + gelu, float4 stores --------
    int epy = pg >> 5, epx = pg & 31;
    int gy  = ty0 + epy;
    #pragma unroll
    for (int oo = 0; oo < 4; oo++) {
        int o = og + oo;
        float bv = bs[o];
        float* op = dst + ((bb * CH + o) << 16) + (gy << 8) + tx0 + epx;
        float v[8];
        #pragma unroll
        for (int j = 0; j < 4; j++) unpack2(acc[oo][j], v[2*j], v[2*j+1]);
        float4 r0 = make_float4(gelu_f(v[0]+bv), gelu_f(v[1]+bv), gelu_f(v[2]+bv), gelu_f(v[3]+bv));
        float4 r1 = make_float4(gelu_f(v[4]+bv), gelu_f(v[5]+bv), gelu_f(v[6]+bv), gelu_f(v[7]+bv));
        *reinterpret_cast<float4*>(op)     = r0;
        *reinterpret_cast<float4*>(op + 4) = r1;
    }
}

// ---------------- kernel 1: first layer (1 -> 32 ch) + gelu ----------------
__global__ void k_first(const float* __restrict__ x,
                        const float* __restrict__ ci, const float* __restrict__ bi,
                        const float* __restrict__ ai, const float* __restrict__ bias_i,
                        float sign)
{
    __shared__ float w[128];
    int tid = threadIdx.y * 32 + threadIdx.x;
    if (tid < 128) {
        w[tid] = (tid < 32) ? ci[tid]
               : (tid < 64) ? bi[tid - 32]
               : (tid < 96) ? ai[tid - 64]
                            : bias_i[tid - 96];
    }
    __syncthreads();

    int gx = blockIdx.x * 32 + threadIdx.x;
    int gy = blockIdx.y * 8  + threadIdx.y;
    int b  = blockIdx.z;

    const float* xb = x + (b << 16);
    int xm = (gx + 255) & 255, xq = (gx + 1) & 255;
    int ym = (gy + 255) & 255, yq = (gy + 1) & 255;

    float ctr = xb[(gy << 8) + gx];
    float nb  = xb[(ym << 8) + gx] + xb[(yq << 8) + gx]
              + xb[(gy << 8) + xm] + xb[(gy << 8) + xq];
    float dg  = xb[(ym << 8) + xm] + xb[(ym << 8) + xq]
              + xb[(yq << 8) + xm] + xb[(yq << 8) + xq];
    ctr *= sign; nb *= sign; dg *= sign;

    float* outp = g_bufA + ((b * CH) << 16) + (gy << 8) + gx;
    #pragma unroll
    for (int o = 0; o < 32; o++) {
        float v = w[o] * ctr + w[32 + o] * nb + w[64 + o] * dg + w[96 + o];
        outp[o << 16] = gelu_f(v);
    }
}

// ---------------- kernel 3: last layer (32 -> 1 ch), antisym combine ----------------
#define HS1 (32*10*34)
__global__ void k_last(const float* __restrict__ co, const float* __restrict__ bo,
                       const float* __restrict__ ao, float* __restrict__ out, int mode)
{
    __shared__ float Hs[HS1];
    __shared__ float ws[96];
    int tx = threadIdx.x, ty = threadIdx.y;
    int tid = ty * 32 + tx;
    int tx0 = blockIdx.x * 32, ty0 = blockIdx.y * 8, b = blockIdx.z;
    const float* inb = g_bufA + ((b * CH) << 16);

    for (int t = tid; t < HS1; t += 256) {
        int i   = t / 340;
        int rem = t - i * 340;
        int r   = rem / 34;
        int cc  = rem - r * 34;
        int gy  = (ty0 + r + 255) & 255;
        int gx  = (tx0 + cc + 255) & 255;
        Hs[t] = inb[(i << 16) + (gy << 8) + gx];
    }
    if (tid < 96) {
        ws[tid] = (tid < 32) ? co[tid] : (tid < 64) ? bo[tid - 32] : ao[tid - 64];
    }
    __syncthreads();

    int base = (ty + 1) * 34 + tx + 1;
    float acc = 0.f;
    #pragma unroll 4
    for (int i = 0; i < 32; i++) {
        const float* h = Hs + i * 340;
        float ctr = h[base];
        float nb  = h[base - 34] + h[base + 34] + h[base - 1]  + h[base + 1];
        float dg  = h[base - 35] + h[base + 35] + h[base - 33] + h[base + 33];
        acc += ws[i] * ctr + ws[32 + i] * nb + ws[64 + i] * dg;
    }

    int gy = ty0 + ty, gx = tx0 + tx;
    int oidx = (b << 16) + (gy << 8) + gx;
    if (mode == 0) out[oidx] = 0.5f * acc;
    else           out[oidx] -= 0.5f * acc;
}

// ---------------- launcher ----------------

extern "C" void kernel_launch(void* const* d_in, const int* in_sizes, int n_in,
                              void* d_out, int out_size)
{
    const float* x      = (const float*)d_in[0];
    const float* ai     = (const float*)d_in[1];
    const float* ao     = (const float*)d_in[2];
    const float* a      = (const float*)d_in[3];
    const float* bi     = (const float*)d_in[4];
    const float* bo     = (const float*)d_in[5];
    const float* b      = (const float*)d_in[6];
    const float* ci     = (const float*)d_in[7];
    const float* co     = (const float*)d_in[8];
    const float* c      = (const float*)d_in[9];
    const float* bias_i = (const float*)d_in[10];
    const float* bias   = (const float*)d_in[11];
    float* out = (float*)d_out;

    cudaFuncSetAttribute(k_mid, cudaFuncAttributeMaxDynamicSharedMemorySize, SMEM_BYTES);

    dim3 gridM(8, 16, 32);
    dim3 gridS(8, 32, 32);
    dim3 blkS(32, 8);

    for (int s = 0; s < 2; s++) {
        float sign = s ? -1.f : 1.f;
        k_first<<<gridS, blkS>>>(x, ci, bi, ai, bias_i, sign);
        int dir = 0;
        for (int k = 0; k < DEPTH; k++) {
            k_mid<<<gridM, 512, SMEM_BYTES>>>(a, b, c, bias, k, dir);
            dir ^= 1;
        }
        k_last<<<gridS, blkS>>>(co, bo, ao, out, s);
    }
}

// round 7
// speedup vs baseline: 1.3742x; 1.1728x over previous
#include <cuda_runtime.h>
#include <cuda_bf16.h>
#include <math.h>
#include <stdint.h>

#define L 256
#define CH 32
#define DEPTH 4
#define PLANE (L*L)
#define BUF_ELEMS (32u*CH*PLANE)

__device__ float g_bufA[BUF_ELEMS];
__device__ float g_bufB[BUF_ELEMS];

// ---------------- helpers ----------------

__device__ __forceinline__ uint32_t smem_u32(const void* p) {
    uint32_t a;
    asm("{ .reg .u64 t; cvta.to.shared.u64 t, %1; cvt.u32.u64 %0, t; }" : "=r"(a) : "l"(p));
    return a;
}

__device__ __forceinline__ float gelu_f(float v) {
    return 0.5f * v * (1.0f + erff(v * 0.7071067811865476f));
}

__device__ __forceinline__ void ldm_x4(uint32_t* r, uint32_t addr) {
    asm volatile("ldmatrix.sync.aligned.m8n8.x4.shared.b16 {%0,%1,%2,%3}, [%4];"
        : "=r"(r[0]), "=r"(r[1]), "=r"(r[2]), "=r"(r[3]) : "r"(addr));
}

__device__ __forceinline__ void mma_bf16(float* d, const uint32_t* a, const uint32_t* b) {
    asm volatile("mma.sync.aligned.m16n8k16.row.col.f32.bf16.bf16.f32 "
        "{%0,%1,%2,%3}, {%4,%5,%6,%7}, {%8,%9}, {%0,%1,%2,%3};"
        : "+f"(d[0]), "+f"(d[1]), "+f"(d[2]), "+f"(d[3])
        : "r"(a[0]), "r"(a[1]), "r"(a[2]), "r"(a[3]), "r"(b[0]), "r"(b[1]));
}

// ---------------- k_mid_mma: tensor-core middle layer ----------------
// CTA tile: 8 rows x 16 cols = 128 px. D[128 p][32 o] = A[128][96] x B[32][96]^T.
// A,B stored split-bf16 (hi+lo). Padded row pitch 208 B (104 halves).

#define TROW 8
#define TCOL 16
#define HROW 10
#define HCOLW 18
#define HCHS 181                        // padded fp32 per channel
#define APITCH 208                      // bytes per A/B row (96*2 used, pad to 13*16)
#define A0_OFF 23296                    // halo = 32*181*4 = 23168
#define A1_OFF (A0_OFF + 128*APITCH)    // +26624 = 49920
#define B0_OFF (A1_OFF + 128*APITCH)    // 76544
#define B1_OFF (B0_OFF + 32*APITCH)     // 83200
#define BIAS_OFF (B1_OFF + 32*APITCH)   // 89856
#define SMEM_TOTAL (BIAS_OFF + 128)     // 89984
#define DS_PITCH 132                    // fp32, D staging (reuses A0 region)

__device__ __forceinline__ void store_split(char* A0, char* A1, int p, int k, float v0, float v1) {
    uint32_t off = (uint32_t)(p * APITCH + k * 2);     // k even -> 4B aligned
    __nv_bfloat16 h0 = __float2bfloat16(v0);
    __nv_bfloat16 h1 = __float2bfloat16(v1);
    float r0 = v0 - __bfloat162float(h0);
    float r1 = v1 - __bfloat162float(h1);
    __nv_bfloat162 hi; hi.x = h0; hi.y = h1;
    __nv_bfloat162 lo; lo.x = __float2bfloat16(r0); lo.y = __float2bfloat16(r1);
    *reinterpret_cast<__nv_bfloat162*>(A0 + off) = hi;
    *reinterpret_cast<__nv_bfloat162*>(A1 + off) = lo;
}

__global__ void __launch_bounds__(256, 2)
k_mid_mma(const float* __restrict__ wa_g, const float* __restrict__ wb_g,
          const float* __restrict__ wc_g, const float* __restrict__ bias_g,
          int layer, int dir)
{
    extern __shared__ char smc[];
    float* Hs = (float*)smc;
    char* A0 = smc + A0_OFF;
    char* A1 = smc + A1_OFF;
    char* B0 = smc + B0_OFF;
    char* B1 = smc + B1_OFF;
    float* bias_s = (float*)(smc + BIAS_OFF);
    uint32_t smem_base = smem_u32(smc);

    const float* src = dir ? g_bufB : g_bufA;
    float*       dst = dir ? g_bufA : g_bufB;

    int tid = threadIdx.x;
    int wid = tid >> 5;
    int lane = tid & 31;
    int tx0 = blockIdx.x * TCOL, ty0 = blockIdx.y * TROW, bb = blockIdx.z;

    // -------- halo load (periodic wrap): [32 ch][10 r][18 c], pitch 181 --------
    const float* inb = src + ((bb * CH) << 16);
    for (int t = tid; t < 32 * HROW * HCOLW; t += 256) {
        int i   = t / 180;
        int rem = t - i * 180;
        int r   = rem / 18;
        int c   = rem - r * 18;
        int gy  = (ty0 + r + 255) & 255;
        int gx  = (tx0 + c + 255) & 255;
        Hs[i * HCHS + r * 18 + c] = inb[(i << 16) + (gy << 8) + gx];
    }
    // -------- weights: split bf16 hi/lo, row-major [o][k] --------
    {
        const float* wc = wc_g + layer * 1024;
        const float* wb = wb_g + layer * 1024;
        const float* wa = wa_g + layer * 1024;
        for (int idx = tid; idx < 96 * 32; idx += 256) {
            int o = idx & 31, kk = idx >> 5;
            const float* ws = (kk < 32) ? wc : (kk < 64) ? wb : wa;
            float v = ws[(o << 5) + (kk & 31)];
            __nv_bfloat16 h0 = __float2bfloat16(v);
            float r = v - __bfloat162float(h0);
            uint32_t off = (uint32_t)(o * APITCH + kk * 2);
            *reinterpret_cast<__nv_bfloat16*>(B0 + off) = h0;
            *reinterpret_cast<__nv_bfloat16*>(B1 + off) = __float2bfloat16(r);
        }
        if (tid < 32) bias_s[tid] = bias_g[layer * 32 + tid];
    }
    __syncthreads();

    // -------- build A: thread pair per pixel, 16 channels each --------
    {
        int p = tid >> 1, h = tid & 1;
        int pr = p >> 4, pc = p & 15;
        const int base = (pr + 1) * 18 + pc + 1;
        #pragma unroll
        for (int ii = 0; ii < 16; ii += 2) {
            int i = h * 16 + ii;
            const float* h0p = Hs + i * HCHS;
            const float* h1p = Hs + (i + 1) * HCHS;
            float c0 = h0p[base];
            float n0 = h0p[base - 18] + h0p[base + 18] + h0p[base - 1] + h0p[base + 1];
            float d0 = h0p[base - 19] + h0p[base + 19] + h0p[base - 17] + h0p[base + 17];
            float c1 = h1p[base];
            float n1 = h1p[base - 18] + h1p[base + 18] + h1p[base - 1] + h1p[base + 1];
            float d1 = h1p[base - 19] + h1p[base + 19] + h1p[base - 17] + h1p[base + 17];
            store_split(A0, A1, p, i,      c0, c1);
            store_split(A0, A1, p, 32 + i, n0, n1);
            store_split(A0, A1, p, 64 + i, d0, d1);
        }
    }
    __syncthreads();

    // -------- warp MMA: warp wid owns px [16*wid, 16*wid+16) x all 32 o --------
    float acc[4][4] = {};
    {
        int p0 = wid << 4;
        // A lane address: rows p0 + (lane&15), k-halfsel (lane>>4)
        uint32_t aAoff = (uint32_t)((p0 + (lane & 15)) * APITCH + ((lane >> 4) & 1) * 16);
        uint32_t aA0 = smem_base + A0_OFF + aAoff;
        uint32_t aA1 = smem_base + A1_OFF + aAoff;
        // B lane address (x4 covers 2 ntiles): rows ((lane>>4)<<3)+(lane&7), k-halfsel (lane>>3)&1
        uint32_t aBoff = (uint32_t)(((((lane >> 4) << 3) + (lane & 7)) * APITCH) + ((lane >> 3) & 1) * 16);
        uint32_t aB0 = smem_base + B0_OFF + aBoff;
        uint32_t aB1 = smem_base + B1_OFF + aBoff;

        #pragma unroll
        for (int kc = 0; kc < 6; kc++) {
            uint32_t kb = (uint32_t)(kc * 32);
            uint32_t ah[4], al[4], bh[8], bl[8];
            ldm_x4(ah, aA0 + kb);
            ldm_x4(al, aA1 + kb);
            ldm_x4(bh,     aB0 + kb);                 // ntiles 0,1 (o 0-15)
            ldm_x4(bh + 4, aB0 + kb + 16 * APITCH);   // ntiles 2,3 (o 16-31)
            ldm_x4(bl,     aB1 + kb);
            ldm_x4(bl + 4, aB1 + kb + 16 * APITCH);
            #pragma unroll
            for (int nt = 0; nt < 4; nt++) {
                mma_bf16(acc[nt], ah, &bh[nt * 2]);
                mma_bf16(acc[nt], ah, &bl[nt * 2]);
                mma_bf16(acc[nt], al, &bh[nt * 2]);
            }
        }
    }
    __syncthreads();    // all warps done reading A0 region

    // -------- stage D to smem (reuse A0): Ds[o][p], pitch 132 --------
    {
        float* Ds = (float*)(smc + A0_OFF);
        int p0 = wid << 4;
        int r  = lane >> 2, c2 = (lane & 3) << 1;
        #pragma unroll
        for (int nt = 0; nt < 4; nt++) {
            int o = (nt << 3) + c2;
            Ds[o * DS_PITCH + p0 + r]           = acc[nt][0];
            Ds[(o + 1) * DS_PITCH + p0 + r]     = acc[nt][1];
            Ds[o * DS_PITCH + p0 + r + 8]       = acc[nt][2];
            Ds[(o + 1) * DS_PITCH + p0 + r + 8] = acc[nt][3];
        }
    }
    __syncthreads();

    // -------- output: thread t -> (o = t>>3, tile row g = t&7), coalesced float4 --------
    {
        const float* Ds = (const float*)(smc + A0_OFF);
        int o = tid >> 3, g = tid & 7;
        float bv = bias_s[o];
        const float* row = Ds + o * DS_PITCH + (g << 4);
        float* ob = dst + ((bb * CH + o) << 16) + ((ty0 + g) << 8) + tx0;
        #pragma unroll
        for (int j = 0; j < 4; j++) {
            float4 v;
            v.x = gelu_f(row[j * 4 + 0] + bv);
            v.y = gelu_f(row[j * 4 + 1] + bv);
            v.z = gelu_f(row[j * 4 + 2] + bv);
            v.w = gelu_f(row[j * 4 + 3] + bv);
            *reinterpret_cast<float4*>(ob + j * 4) = v;
        }
    }
}

// ---------------- kernel 1: first layer (1 -> 32 ch) + gelu ----------------
__global__ void k_first(const float* __restrict__ x,
                        const float* __restrict__ ci, const float* __restrict__ bi,
                        const float* __restrict__ ai, const float* __restrict__ bias_i,
                        float sign)
{
    __shared__ float w[128];
    int tid = threadIdx.y * 32 + threadIdx.x;
    if (tid < 128) {
        w[tid] = (tid < 32) ? ci[tid]
               : (tid < 64) ? bi[tid - 32]
               : (tid < 96) ? ai[tid - 64]
                            : bias_i[tid - 96];
    }
    __syncthreads();

    int gx = blockIdx.x * 32 + threadIdx.x;
    int gy = blockIdx.y * 8  + threadIdx.y;
    int b  = blockIdx.z;

    const float* xb = x + (b << 16);
    int xm = (gx + 255) & 255, xq = (gx + 1) & 255;
    int ym = (gy + 255) & 255, yq = (gy + 1) & 255;

    float ctr = xb[(gy << 8) + gx];
    float nb  = xb[(ym << 8) + gx] + xb[(yq << 8) + gx]
              + xb[(gy << 8) + xm] + xb[(gy << 8) + xq];
    float dg  = xb[(ym << 8) + xm] + xb[(ym << 8) + xq]
              + xb[(yq << 8) + xm] + xb[(yq << 8) + xq];
    ctr *= sign; nb *= sign; dg *= sign;

    float* outp = g_bufA + ((b * CH) << 16) + (gy << 8) + gx;
    #pragma unroll
    for (int o = 0; o < 32; o++) {
        float v = w[o] * ctr + w[32 + o] * nb + w[64 + o] * dg + w[96 + o];
        outp[o << 16] = gelu_f(v);
    }
}

// ---------------- kernel 3: last layer (32 -> 1 ch), antisym combine ----------------
#define HS1 (32*10*34)
__global__ void k_last(const float* __restrict__ co, const float* __restrict__ bo,
                       const float* __restrict__ ao, float* __restrict__ out, int mode)
{
    __shared__ float Hs[HS1];
    __shared__ float ws[96];
    int tx = threadIdx.x, ty = threadIdx.y;
    int tid = ty * 32 + tx;
    int tx0 = blockIdx.x * 32, ty0 = blockIdx.y * 8, b = blockIdx.z;
    const float* inb = g_bufA + ((b * CH) << 16);

    for (int t = tid; t < HS1; t += 256) {
        int i   = t / 340;
        int rem = t - i * 340;
        int r   = rem / 34;
        int cc  = rem - r * 34;
        int gy  = (ty0 + r + 255) & 255;
        int gx  = (tx0 + cc + 255) & 255;
        Hs[t] = inb[(i << 16) + (gy << 8) + gx];
    }
    if (tid < 96) {
        ws[tid] = (tid < 32) ? co[tid] : (tid < 64) ? bo[tid - 32] : ao[tid - 64];
    }
    __syncthreads();

    int base = (ty + 1) * 34 + tx + 1;
    float acc = 0.f;
    #pragma unroll 4
    for (int i = 0; i < 32; i++) {
        const float* h = Hs + i * 340;
        float ctr = h[base];
        float nb  = h[base - 34] + h[base + 34] + h[base - 1]  + h[base + 1];
        float dg  = h[base - 35] + h[base + 35] + h[base - 33] + h[base + 33];
        acc += ws[i] * ctr + ws[32 + i] * nb + ws[64 + i] * dg;
    }

    int gy = ty0 + ty, gx = tx0 + tx;
    int oidx = (b << 16) + (gy << 8) + gx;
    if (mode == 0) out[oidx] = 0.5f * acc;
    else           out[oidx] -= 0.5f * acc;
}

// ---------------- launcher ----------------

extern "C" void kernel_launch(void* const* d_in, const int* in_sizes, int n_in,
                              void* d_out, int out_size)
{
    const float* x      = (const float*)d_in[0];
    const float* ai     = (const float*)d_in[1];
    const float* ao     = (const float*)d_in[2];
    const float* a      = (const float*)d_in[3];
    const float* bi     = (const float*)d_in[4];
    const float* bo     = (const float*)d_in[5];
    const float* b      = (const float*)d_in[6];
    const float* ci     = (const float*)d_in[7];
    const float* co     = (const float*)d_in[8];
    const float* c      = (const float*)d_in[9];
    const float* bias_i = (const float*)d_in[10];
    const float* bias   = (const float*)d_in[11];
    float* out = (float*)d_out;

    cudaFuncSetAttribute(k_mid_mma, cudaFuncAttributeMaxDynamicSharedMemorySize, SMEM_TOTAL);

    dim3 gridM(16, 32, 32);     // 16 x-tiles(16 px), 32 y-tiles(8 px), 32 batch
    dim3 gridS(8, 32, 32);
    dim3 blkS(32, 8);

    for (int s = 0; s < 2; s++) {
        float sign = s ? -1.f : 1.f;
        k_first<<<gridS, blkS>>>(x, ci, bi, ai, bias_i, sign);
        int dir = 0;
        for (int k = 0; k < DEPTH; k++) {
            k_mid_mma<<<gridM, 256, SMEM_TOTAL>>>(a, b, c, bias, k, dir);
            dir ^= 1;
        }
        k_last<<<gridS, blkS>>>(co, bo, ao, out, s);
    }
}

// round 8
// speedup vs baseline: 2.1948x; 1.5972x over previous
#include <cuda_runtime.h>
#include <cuda_bf16.h>
#include <math.h>
#include <stdint.h>

#define L 256
#define CH 32
#define DEPTH 4
#define PLANE (L*L)
#define BUF_ELEMS (32u*CH*PLANE)

__device__ float g_bufA[BUF_ELEMS];
__device__ float g_bufB[BUF_ELEMS];

// ---------------- helpers ----------------

__device__ __forceinline__ uint32_t smem_u32(const void* p) {
    uint32_t a;
    asm("{ .reg .u64 t; cvta.to.shared.u64 t, %1; cvt.u32.u64 %0, t; }" : "=r"(a) : "l"(p));
    return a;
}

__device__ __forceinline__ float gelu_f(float v) {
    return 0.5f * v * (1.0f + erff(v * 0.7071067811865476f));
}

__device__ __forceinline__ void ldm_x4(uint32_t* r, uint32_t addr) {
    asm volatile("ldmatrix.sync.aligned.m8n8.x4.shared.b16 {%0,%1,%2,%3}, [%4];"
        : "=r"(r[0]), "=r"(r[1]), "=r"(r[2]), "=r"(r[3]) : "r"(addr));
}

__device__ __forceinline__ void mma_bf16(float* d, const uint32_t* a, const uint32_t* b) {
    asm volatile("mma.sync.aligned.m16n8k16.row.col.f32.bf16.bf16.f32 "
        "{%0,%1,%2,%3}, {%4,%5,%6,%7}, {%8,%9}, {%0,%1,%2,%3};"
        : "+f"(d[0]), "+f"(d[1]), "+f"(d[2]), "+f"(d[3])
        : "r"(a[0]), "r"(a[1]), "r"(a[2]), "r"(a[3]), "r"(b[0]), "r"(b[1]));
}

// ---------------- k_mid_mma: implicit-conv tensor-core middle layer ----------------
// CTA tile: 16x16 = 256 px. D[256 p][32 o] = sum over 9 offsets of
//   Halo[p+off][32 ch] x Bclass(off)[32 o][32 ch]^T  (split-bf16, 3 products)
// Halo stored channel-contiguous: position stride 80 B (64 data + 16 pad,
// conflict-free for ldmatrix rows), row stride 18*80 = 1440 B.

#define CPITCH 80
#define RPITCH 1440
#define BPITCH 208
#define H0_OFF 0
#define H1_OFF 25920                  // 18*1440
#define B0_OFF 51840
#define B1_OFF 58496                  // +32*208
#define BIAS_OFF 65152
#define SMEM_TOTAL 65344

__global__ void __launch_bounds__(256, 2)
k_mid_mma(const float* __restrict__ wa_g, const float* __restrict__ wb_g,
          const float* __restrict__ wc_g, const float* __restrict__ bias_g,
          int layer, int dir)
{
    extern __shared__ char smc[];
    float* bias_s = (float*)(smc + BIAS_OFF);
    uint32_t smem_base = smem_u32(smc);

    const float* src = dir ? g_bufB : g_bufA;
    float*       dst = dir ? g_bufA : g_bufB;

    int tid = threadIdx.x;
    int wid = tid >> 5;
    int lane = tid & 31;
    int tx0 = blockIdx.x * 16, ty0 = blockIdx.y * 16, bb = blockIdx.z;

    // -------- weights: split bf16 hi/lo, [o][kk] kk = class*32 + ch --------
    {
        const float* wc = wc_g + layer * 1024;
        const float* wb = wb_g + layer * 1024;
        const float* wa = wa_g + layer * 1024;
        char* B0c = smc + B0_OFF;
        char* B1c = smc + B1_OFF;
        for (int idx = tid; idx < 96 * 32; idx += 256) {
            int o = idx & 31, kk = idx >> 5;
            const float* ws = (kk < 32) ? wc : (kk < 64) ? wb : wa;
            float v = ws[(o << 5) + (kk & 31)];
            __nv_bfloat16 h0 = __float2bfloat16(v);
            float r = v - __bfloat162float(h0);
            *reinterpret_cast<__nv_bfloat16*>(B0c + o * BPITCH + kk * 2) = h0;
            *reinterpret_cast<__nv_bfloat16*>(B1c + o * BPITCH + kk * 2) = __float2bfloat16(r);
        }
        if (tid < 32) bias_s[tid] = bias_g[layer * 32 + tid];
    }

    // -------- halo load + split-bf16 store, channel-contiguous --------
    {
        const float* inb = src + ((bb * CH) << 16);
        for (int t = tid; t < 324; t += 256) {
            int r = t / 18, c = t - r * 18;
            int gy = (ty0 + r + 255) & 255;
            int gx = (tx0 + c + 255) & 255;
            const float* g = inb + (gy << 8) + gx;
            char* h0 = smc + H0_OFF + r * RPITCH + c * CPITCH;
            char* h1 = smc + H1_OFF + r * RPITCH + c * CPITCH;
            #pragma unroll
            for (int ch2 = 0; ch2 < 16; ch2++) {
                float v0 = g[(ch2 * 2) << 16];
                float v1 = g[(ch2 * 2 + 1) << 16];
                __nv_bfloat16 a0 = __float2bfloat16(v0);
                __nv_bfloat16 a1 = __float2bfloat16(v1);
                __nv_bfloat162 hi; hi.x = a0; hi.y = a1;
                __nv_bfloat162 lo;
                lo.x = __float2bfloat16(v0 - __bfloat162float(a0));
                lo.y = __float2bfloat16(v1 - __bfloat162float(a1));
                *reinterpret_cast<__nv_bfloat162*>(h0 + ch2 * 4) = hi;
                *reinterpret_cast<__nv_bfloat162*>(h1 + ch2 * 4) = lo;
            }
        }
    }
    __syncthreads();

    // -------- MMA: warp owns pixel rows 2*wid, 2*wid+1 (32 px) x 32 o --------
    float acc[2][4][4] = {};
    int pr0 = wid << 1;
    uint32_t laneA = (uint32_t)(((lane & 15) + 1) * CPITCH + (lane >> 4) * 16);
    uint32_t aB  = smem_base + B0_OFF
                 + (uint32_t)(((((lane >> 4) << 3) + (lane & 7)) * BPITCH) + ((lane >> 3) & 1) * 16);
    uint32_t aBl = aB + (B1_OFF - B0_OFF);

    const int DY[9] = {0, -1, 1,  0, 0, -1, 1, -1,  1};
    const int DX[9] = {0,  0, 0, -1, 1, -1, 1,  1, -1};
    int oi = 0;
    #pragma unroll
    for (int cls = 0; cls < 3; cls++) {
        uint32_t bh[2][8], blo[2][8];
        #pragma unroll
        for (int kc = 0; kc < 2; kc++) {
            uint32_t kb = (uint32_t)(cls * 64 + kc * 32);
            ldm_x4(bh[kc],      aB  + kb);
            ldm_x4(bh[kc] + 4,  aB  + kb + 16 * BPITCH);
            ldm_x4(blo[kc],     aBl + kb);
            ldm_x4(blo[kc] + 4, aBl + kb + 16 * BPITCH);
        }
        int noff = cls ? 4 : 1;
        #pragma unroll
        for (int f = 0; f < noff; f++, oi++) {
            int dy = DY[oi], dx = DX[oi];
            uint32_t a0 = smem_base + H0_OFF
                        + (uint32_t)((pr0 + 1 + dy) * RPITCH + dx * CPITCH) + laneA;
            uint32_t a1 = a0 + (H1_OFF - H0_OFF);
            #pragma unroll
            for (int kc = 0; kc < 2; kc++) {
                uint32_t ah0[4], ah1[4], al0[4], al1[4];
                ldm_x4(ah0, a0 + kc * 32);
                ldm_x4(ah1, a0 + RPITCH + kc * 32);
                ldm_x4(al0, a1 + kc * 32);
                ldm_x4(al1, a1 + RPITCH + kc * 32);
                #pragma unroll
                for (int nt = 0; nt < 4; nt++) {
                    mma_bf16(acc[0][nt], ah0, &bh[kc][nt * 2]);
                    mma_bf16(acc[0][nt], al0, &bh[kc][nt * 2]);
                    mma_bf16(acc[0][nt], ah0, &blo[kc][nt * 2]);
                    mma_bf16(acc[1][nt], ah1, &bh[kc][nt * 2]);
                    mma_bf16(acc[1][nt], al1, &bh[kc][nt * 2]);
                    mma_bf16(acc[1][nt], ah1, &blo[kc][nt * 2]);
                }
            }
        }
    }

    // -------- epilogue: bias + gelu, direct sector-aligned STG --------
    {
        int r = lane >> 2, c2 = (lane & 3) << 1;
        #pragma unroll
        for (int nt = 0; nt < 4; nt++) {
            int o = (nt << 3) + c2;
            float b0 = bias_s[o], b1 = bias_s[o + 1];
            #pragma unroll
            for (int t = 0; t < 2; t++) {
                float* bp = dst + ((uint32_t)(bb * CH + o) << 16)
                          + ((uint32_t)(ty0 + pr0 + t) << 8) + tx0;
                bp[r]             = gelu_f(acc[t][nt][0] + b0);
                bp[65536 + r]     = gelu_f(acc[t][nt][1] + b1);
                bp[r + 8]         = gelu_f(acc[t][nt][2] + b0);
                bp[65536 + r + 8] = gelu_f(acc[t][nt][3] + b1);
            }
        }
    }
}

// ---------------- kernel 1: first layer (1 -> 32 ch) + gelu ----------------
__global__ void k_first(const float* __restrict__ x,
                        const float* __restrict__ ci, const float* __restrict__ bi,
                        const float* __restrict__ ai, const float* __restrict__ bias_i,
                        float sign)
{
    __shared__ float w[128];
    int tid = threadIdx.y * 32 + threadIdx.x;
    if (tid < 128) {
        w[tid] = (tid < 32) ? ci[tid]
               : (tid < 64) ? bi[tid - 32]
               : (tid < 96) ? ai[tid - 64]
                            : bias_i[tid - 96];
    }
    __syncthreads();

    int gx = blockIdx.x * 32 + threadIdx.x;
    int gy = blockIdx.y * 8  + threadIdx.y;
    int b  = blockIdx.z;

    const float* xb = x + (b << 16);
    int xm = (gx + 255) & 255, xq = (gx + 1) & 255;
    int ym = (gy + 255) & 255, yq = (gy + 1) & 255;

    float ctr = xb[(gy << 8) + gx];
    float nb  = xb[(ym << 8) + gx] + xb[(yq << 8) + gx]
              + xb[(gy << 8) + xm] + xb[(gy << 8) + xq];
    float dg  = xb[(ym << 8) + xm] + xb[(ym << 8) + xq]
              + xb[(yq << 8) + xm] + xb[(yq << 8) + xq];
    ctr *= sign; nb *= sign; dg *= sign;

    float* outp = g_bufA + ((b * CH) << 16) + (gy << 8) + gx;
    #pragma unroll
    for (int o = 0; o < 32; o++) {
        float v = w[o] * ctr + w[32 + o] * nb + w[64 + o] * dg + w[96 + o];
        outp[o << 16] = gelu_f(v);
    }
}

// ---------------- kernel 3: last layer (32 -> 1 ch), antisym combine ----------------
#define HS1 (32*10*34)
__global__ void k_last(const float* __restrict__ co, const float* __restrict__ bo,
                       const float* __restrict__ ao, float* __restrict__ out, int mode)
{
    __shared__ float Hs[HS1];
    __shared__ float ws[96];
    int tx = threadIdx.x, ty = threadIdx.y;
    int tid = ty * 32 + tx;
    int tx0 = blockIdx.x * 32, ty0 = blockIdx.y * 8, b = blockIdx.z;
    const float* inb = g_bufA + ((b * CH) << 16);

    for (int t = tid; t < HS1; t += 256) {
        int i   = t / 340;
        int rem = t - i * 340;
        int r   = rem / 34;
        int cc  = rem - r * 34;
        int gy  = (ty0 + r + 255) & 255;
        int gx  = (tx0 + cc + 255) & 255;
        Hs[t] = inb[(i << 16) + (gy << 8) + gx];
    }
    if (tid < 96) {
        ws[tid] = (tid < 32) ? co[tid] : (tid < 64) ? bo[tid - 32] : ao[tid - 64];
    }
    __syncthreads();

    int base = (ty + 1) * 34 + tx + 1;
    float acc = 0.f;
    #pragma unroll 4
    for (int i = 0; i < 32; i++) {
        const float* h = Hs + i * 340;
        float ctr = h[base];
        float nb  = h[base - 34] + h[base + 34] + h[base - 1]  + h[base + 1];
        float dg  = h[base - 35] + h[base + 35] + h[base - 33] + h[base + 33];
        acc += ws[i] * ctr + ws[32 + i] * nb + ws[64 + i] * dg;
    }

    int gy = ty0 + ty, gx = tx0 + tx;
    int oidx = (b << 16) + (gy << 8) + gx;
    if (mode == 0) out[oidx] = 0.5f * acc;
    else           out[oidx] -= 0.5f * acc;
}

// ---------------- launcher ----------------

extern "C" void kernel_launch(void* const* d_in, const int* in_sizes, int n_in,
                              void* d_out, int out_size)
{
    const float* x      = (const float*)d_in[0];
    const float* ai     = (const float*)d_in[1];
    const float* ao     = (const float*)d_in[2];
    const float* a      = (const float*)d_in[3];
    const float* bi     = (const float*)d_in[4];
    const float* bo     = (const float*)d_in[5];
    const float* b      = (const float*)d_in[6];
    const float* ci     = (const float*)d_in[7];
    const float* co     = (const float*)d_in[8];
    const float* c      = (const float*)d_in[9];
    const float* bias_i = (const float*)d_in[10];
    const float* bias   = (const float*)d_in[11];
    float* out = (float*)d_out;

    cudaFuncSetAttribute(k_mid_mma, cudaFuncAttributeMaxDynamicSharedMemorySize, SMEM_TOTAL);

    dim3 gridM(16, 16, 32);     // 16x16 px tiles
    dim3 gridS(8, 32, 32);
    dim3 blkS(32, 8);

    for (int s = 0; s < 2; s++) {
        float sign = s ? -1.f : 1.f;
        k_first<<<gridS, blkS>>>(x, ci, bi, ai, bias_i, sign);
        int dir = 0;
        for (int k = 0; k < DEPTH; k++) {
            k_mid_mma<<<gridM, 256, SMEM_TOTAL>>>(a, b, c, bias, k, dir);
            dir ^= 1;
        }
        k_last<<<gridS, blkS>>>(co, bo, ao, out, s);
    }
}

// round 9
// speedup vs baseline: 2.3151x; 1.0548x over previous
#include <cuda_runtime.h>
#include <cuda_bf16.h>
#include <math.h>
#include <stdint.h>

#define L 256
#define CH 32
#define DEPTH 4
#define PLANE (L*L)
#define BUF_ELEMS (32u*CH*PLANE)

__device__ float g_bufA[BUF_ELEMS];
__device__ float g_bufB[BUF_ELEMS];

// ---------------- helpers ----------------

__device__ __forceinline__ uint32_t smem_u32(const void* p) {
    uint32_t a;
    asm("{ .reg .u64 t; cvta.to.shared.u64 t, %1; cvt.u32.u64 %0, t; }" : "=r"(a) : "l"(p));
    return a;
}

__device__ __forceinline__ float gelu_f(float v) {
    return 0.5f * v * (1.0f + erff(v * 0.7071067811865476f));
}

__device__ __forceinline__ void ldm_x4(uint32_t* r, uint32_t addr) {
    asm volatile("ldmatrix.sync.aligned.m8n8.x4.shared.b16 {%0,%1,%2,%3}, [%4];"
        : "=r"(r[0]), "=r"(r[1]), "=r"(r[2]), "=r"(r[3]) : "r"(addr));
}

__device__ __forceinline__ void mma_bf16(float* d, const uint32_t* a, const uint32_t* b) {
    asm volatile("mma.sync.aligned.m16n8k16.row.col.f32.bf16.bf16.f32 "
        "{%0,%1,%2,%3}, {%4,%5,%6,%7}, {%8,%9}, {%0,%1,%2,%3};"
        : "+f"(d[0]), "+f"(d[1]), "+f"(d[2]), "+f"(d[3])
        : "r"(a[0]), "r"(a[1]), "r"(a[2]), "r"(a[3]), "r"(b[0]), "r"(b[1]));
}

// ---------------- k_mid_mma: implicit-conv tensor-core middle layer ----------------
// CTA tile: 16x16 = 256 px. D[256 p][32 o] = sum over 9 offsets of
//   Halo[p+off][32 ch] x Bclass(off)[32 o][32 ch]^T  (split-bf16, 3 products)
// Halo channel-contiguous: position stride 80 B, row stride 1440 B.
// Mainloop slides over 4 physical halo rows x 3 dx; each A fragment feeds all
// target rows that reference it (12-24 MMAs per 2 ldmatrix.x4).

#define CPITCH 80
#define RPITCH 1440
#define BPITCH 208
#define H0_OFF 0
#define H1_OFF 25920                  // 18*1440
#define B0_OFF 51840
#define B1_OFF 58496                  // +32*208
#define BIAS_OFF 65152
#define SMEM_TOTAL 65344

__global__ void __launch_bounds__(256, 2)
k_mid_mma(const float* __restrict__ wa_g, const float* __restrict__ wb_g,
          const float* __restrict__ wc_g, const float* __restrict__ bias_g,
          int layer, int dir)
{
    extern __shared__ char smc[];
    float* bias_s = (float*)(smc + BIAS_OFF);
    uint32_t smem_base = smem_u32(smc);

    const float* src = dir ? g_bufB : g_bufA;
    float*       dst = dir ? g_bufA : g_bufB;

    int tid = threadIdx.x;
    int wid = tid >> 5;
    int lane = tid & 31;
    int tx0 = blockIdx.x * 16, ty0 = blockIdx.y * 16, bb = blockIdx.z;

    // -------- weights: split bf16 hi/lo, [o][kk] kk = class*32 + ch --------
    {
        const float* wc = wc_g + layer * 1024;
        const float* wb = wb_g + layer * 1024;
        const float* wa = wa_g + layer * 1024;
        char* B0c = smc + B0_OFF;
        char* B1c = smc + B1_OFF;
        for (int idx = tid; idx < 96 * 32; idx += 256) {
            int o = idx & 31, kk = idx >> 5;
            const float* ws = (kk < 32) ? wc : (kk < 64) ? wb : wa;
            float v = ws[(o << 5) + (kk & 31)];
            __nv_bfloat16 h0 = __float2bfloat16(v);
            float r = v - __bfloat162float(h0);
            *reinterpret_cast<__nv_bfloat16*>(B0c + o * BPITCH + kk * 2) = h0;
            *reinterpret_cast<__nv_bfloat16*>(B1c + o * BPITCH + kk * 2) = __float2bfloat16(r);
        }
        if (tid < 32) bias_s[tid] = bias_g[layer * 32 + tid];
    }

    // -------- halo load + split-bf16 store, channel-contiguous --------
    {
        const float* inb = src + ((bb * CH) << 16);
        for (int t = tid; t < 324; t += 256) {
            int r = t / 18, c = t - r * 18;
            int gy = (ty0 + r + 255) & 255;
            int gx = (tx0 + c + 255) & 255;
            const float* g = inb + (gy << 8) + gx;
            char* h0 = smc + H0_OFF + r * RPITCH + c * CPITCH;
            char* h1 = smc + H1_OFF + r * RPITCH + c * CPITCH;
            #pragma unroll
            for (int ch2 = 0; ch2 < 16; ch2++) {
                float v0 = g[(ch2 * 2) << 16];
                float v1 = g[(ch2 * 2 + 1) << 16];
                __nv_bfloat16 a0 = __float2bfloat16(v0);
                __nv_bfloat16 a1 = __float2bfloat16(v1);
                __nv_bfloat162 hi; hi.x = a0; hi.y = a1;
                __nv_bfloat162 lo;
                lo.x = __float2bfloat16(v0 - __bfloat162float(a0));
                lo.y = __float2bfloat16(v1 - __bfloat162float(a1));
                *reinterpret_cast<__nv_bfloat162*>(h0 + ch2 * 4) = hi;
                *reinterpret_cast<__nv_bfloat162*>(h1 + ch2 * 4) = lo;
            }
        }
    }
    __syncthreads();

    // -------- MMA mainloop --------
    // Warp owns target tile rows pr0, pr0+1 (halo rows hr0=pr0+1, hr0+1),
    // each 16 px wide (M=16 = pixel columns). acc[t] = 16px x 32o for row pr0+t.
    float acc[2][4][4] = {};
    int pr0 = wid << 1;
    int hr0 = pr0 + 1;
    uint32_t laneA = (uint32_t)((lane & 15) * CPITCH + (lane >> 4) * 16);
    uint32_t aB  = smem_base + B0_OFF
                 + (uint32_t)(((((lane >> 4) << 3) + (lane & 7)) * BPITCH) + ((lane >> 3) & 1) * 16);
    uint32_t aBl = aB + (B1_OFF - B0_OFF);

    #pragma unroll
    for (int kc = 0; kc < 2; kc++) {
        // B fragments for all 3 classes, this k-chunk
        uint32_t bh[3][8], bl[3][8];
        #pragma unroll
        for (int cls = 0; cls < 3; cls++) {
            uint32_t kb = (uint32_t)(cls * 64 + kc * 32);
            ldm_x4(bh[cls],     aB  + kb);
            ldm_x4(bh[cls] + 4, aB  + kb + 16 * BPITCH);
            ldm_x4(bl[cls],     aBl + kb);
            ldm_x4(bl[cls] + 4, aBl + kb + 16 * BPITCH);
        }

        auto do3 = [&](int t, int cls, const uint32_t* ah, const uint32_t* al) {
            #pragma unroll
            for (int nt = 0; nt < 4; nt++) mma_bf16(acc[t][nt], ah, &bh[cls][nt * 2]);
            #pragma unroll
            for (int nt = 0; nt < 4; nt++) mma_bf16(acc[t][nt], al, &bh[cls][nt * 2]);
            #pragma unroll
            for (int nt = 0; nt < 4; nt++) mma_bf16(acc[t][nt], ah, &bl[cls][nt * 2]);
        };

        // slide over 4 physical rows x 3 dx; each fragment serves 1-2 target rows
        #pragma unroll
        for (int r = 0; r < 4; r++) {
            #pragma unroll
            for (int d = 0; d < 3; d++) {
                uint32_t a0 = smem_base + H0_OFF
                            + (uint32_t)((hr0 - 1 + r) * RPITCH + d * CPITCH + kc * 32) + laneA;
                uint32_t ah[4], al[4];
                ldm_x4(ah, a0);
                ldm_x4(al, a0 + (H1_OFF - H0_OFF));
                if (r <= 2) {   // target t=0: dy = r-1
                    const int dy = r - 1;
                    const int cls = (dy == 0 && d == 1) ? 0 : ((dy == 0 || d == 1) ? 1 : 2);
                    do3(0, cls, ah, al);
                }
                if (r >= 1) {   // target t=1: dy = r-2
                    const int dy = r - 2;
                    const int cls = (dy == 0 && d == 1) ? 0 : ((dy == 0 || d == 1) ? 1 : 2);
                    do3(1, cls, ah, al);
                }
            }
        }
    }

    // -------- epilogue: bias + gelu, direct sector-aligned STG --------
    {
        int r = lane >> 2, c2 = (lane & 3) << 1;
        #pragma unroll
        for (int nt = 0; nt < 4; nt++) {
            int o = (nt << 3) + c2;
            float b0 = bias_s[o], b1 = bias_s[o + 1];
            #pragma unroll
            for (int t = 0; t < 2; t++) {
                float* bp = dst + ((uint32_t)(bb * CH + o) << 16)
                          + ((uint32_t)(ty0 + pr0 + t) << 8) + tx0;
                bp[r]             = gelu_f(acc[t][nt][0] + b0);
                bp[65536 + r]     = gelu_f(acc[t][nt][1] + b1);
                bp[r + 8]         = gelu_f(acc[t][nt][2] + b0);
                bp[65536 + r + 8] = gelu_f(acc[t][nt][3] + b1);
            }
        }
    }
}

// ---------------- kernel 1: first layer (1 -> 32 ch) + gelu ----------------
__global__ void k_first(const float* __restrict__ x,
                        const float* __restrict__ ci, const float* __restrict__ bi,
                        const float* __restrict__ ai, const float* __restrict__ bias_i,
                        float sign)
{
    __shared__ float w[128];
    int tid = threadIdx.y * 32 + threadIdx.x;
    if (tid < 128) {
        w[tid] = (tid < 32) ? ci[tid]
               : (tid < 64) ? bi[tid - 32]
               : (tid < 96) ? ai[tid - 64]
                            : bias_i[tid - 96];
    }
    __syncthreads();

    int gx = blockIdx.x * 32 + threadIdx.x;
    int gy = blockIdx.y * 8  + threadIdx.y;
    int b  = blockIdx.z;

    const float* xb = x + (b << 16);
    int xm = (gx + 255) & 255, xq = (gx + 1) & 255;
    int ym = (gy + 255) & 255, yq = (gy + 1) & 255;

    float ctr = xb[(gy << 8) + gx];
    float nb  = xb[(ym << 8) + gx] + xb[(yq << 8) + gx]
              + xb[(gy << 8) + xm] + xb[(gy << 8) + xq];
    float dg  = xb[(ym << 8) + xm] + xb[(ym << 8) + xq]
              + xb[(yq << 8) + xm] + xb[(yq << 8) + xq];
    ctr *= sign; nb *= sign; dg *= sign;

    float* outp = g_bufA + ((b * CH) << 16) + (gy << 8) + gx;
    #pragma unroll
    for (int o = 0; o < 32; o++) {
        float v = w[o] * ctr + w[32 + o] * nb + w[64 + o] * dg + w[96 + o];
        outp[o << 16] = gelu_f(v);
    }
}

// ---------------- kernel 3: last layer (32 -> 1 ch), antisym combine ----------------
#define HS1 (32*10*34)
__global__ void k_last(const float* __restrict__ co, const float* __restrict__ bo,
                       const float* __restrict__ ao, float* __restrict__ out, int mode)
{
    __shared__ float Hs[HS1];
    __shared__ float ws[96];
    int tx = threadIdx.x, ty = threadIdx.y;
    int tid = ty * 32 + tx;
    int tx0 = blockIdx.x * 32, ty0 = blockIdx.y * 8, b = blockIdx.z;
    const float* inb = g_bufA + ((b * CH) << 16);

    for (int t = tid; t < HS1; t += 256) {
        int i   = t / 340;
        int rem = t - i * 340;
        int r   = rem / 34;
        int cc  = rem - r * 34;
        int gy  = (ty0 + r + 255) & 255;
        int gx  = (tx0 + cc + 255) & 255;
        Hs[t] = inb[(i << 16) + (gy << 8) + gx];
    }
    if (tid < 96) {
        ws[tid] = (tid < 32) ? co[tid] : (tid < 64) ? bo[tid - 32] : ao[tid - 64];
    }
    __syncthreads();

    int base = (ty + 1) * 34 + tx + 1;
    float acc = 0.f;
    #pragma unroll 4
    for (int i = 0; i < 32; i++) {
        const float* h = Hs + i * 340;
        float ctr = h[base];
        float nb  = h[base - 34] + h[base + 34] + h[base - 1]  + h[base + 1];
        float dg  = h[base - 35] + h[base + 35] + h[base - 33] + h[base + 33];
        acc += ws[i] * ctr + ws[32 + i] * nb + ws[64 + i] * dg;
    }

    int gy = ty0 + ty, gx = tx0 + tx;
    int oidx = (b << 16) + (gy << 8) + gx;
    if (mode == 0) out[oidx] = 0.5f * acc;
    else           out[oidx] -= 0.5f * acc;
}

// ---------------- launcher ----------------

extern "C" void kernel_launch(void* const* d_in, const int* in_sizes, int n_in,
                              void* d_out, int out_size)
{
    const float* x      = (const float*)d_in[0];
    const float* ai     = (const float*)d_in[1];
    const float* ao     = (const float*)d_in[2];
    const float* a      = (const float*)d_in[3];
    const float* bi     = (const float*)d_in[4];
    const float* bo     = (const float*)d_in[5];
    const float* b      = (const float*)d_in[6];
    const float* ci     = (const float*)d_in[7];
    const float* co     = (const float*)d_in[8];
    const float* c      = (const float*)d_in[9];
    const float* bias_i = (const float*)d_in[10];
    const float* bias   = (const float*)d_in[11];
    float* out = (float*)d_out;

    cudaFuncSetAttribute(k_mid_mma, cudaFuncAttributeMaxDynamicSharedMemorySize, SMEM_TOTAL);

    dim3 gridM(16, 16, 32);     // 16x16 px tiles
    dim3 gridS(8, 32, 32);
    dim3 blkS(32, 8);

    for (int s = 0; s < 2; s++) {
        float sign = s ? -1.f : 1.f;
        k_first<<<gridS, blkS>>>(x, ci, bi, ai, bias_i, sign);
        int dir = 0;
        for (int k = 0; k < DEPTH; k++) {
            k_mid_mma<<<gridM, 256, SMEM_TOTAL>>>(a, b, c, bias, k, dir);
            dir ^= 1;
        }
        k_last<<<gridS, blkS>>>(co, bo, ao, out, s);
    }
}